// round 1
// baseline (speedup 1.0000x reference)
#include <cuda_runtime.h>
#include <math.h>

// ---------------- problem constants (fixed by reference) ----------------
#define NG   100
#define NPG  500
#define EPG  4000
#define NN   (NG*NPG)      // 50000 nodes
#define NE   (NG*EPG)      // 400000 edges
#define HID  128
#define H4   512
#define PQW  1024          // P (512) || Q (512)
#define KSEL 2000          // ceil(0.5 * 4000)

// output layout (float32, concatenated in reference return order)
#define O_ATT 0
#define O_CW  (NE)
#define O_SW  (2*NE)
#define O_CM  (3*NE)
#define O_EI  (4*NE)           // [2,E]: new_row then new_col
#define O_NM  (6*NE)
#define O_CX  (6*NE + NN)

// ---------------- scratch (__device__ globals; no allocation) ----------------
__device__ float         g_PQ[(size_t)NN * PQW];   // ~205 MB
__device__ unsigned char g_cmask[NE];
__device__ int           g_nm[NN];
__device__ int           g_scan[NN];
__device__ int           g_newid[NN];
__device__ int           g_bsum[128];

// ---------------- helpers ----------------
__device__ __forceinline__ unsigned int f2k(float f) {
    unsigned int u = __float_as_uint(f);
    return (u & 0x80000000u) ? ~u : (u | 0x80000000u);
}
__device__ __forceinline__ float k2f(unsigned int k) {
    unsigned int u = (k & 0x80000000u) ? (k & 0x7FFFFFFFu) : ~k;
    return __uint_as_float(u);
}

// ---------------- K0: zero node-mask ----------------
__global__ void k_zero_nm() {
    int n = blockIdx.x * blockDim.x + threadIdx.x;
    if (n < NN) g_nm[n] = 0;
}

// ---------------- K1: GEMM  PQ[n, 0:512]=emb@W1[:128], PQ[n,512:1024]=emb@W1[128:] ----------------
// M=50000, N=1024, K=128, fp32, BM=BN=64, full-K staged in smem, 256 thr, 4x4 microtile
__global__ __launch_bounds__(256) void k_gemm_pq(const float* __restrict__ emb,
                                                 const float* __restrict__ W1) {
    __shared__ __align__(16) float As[128][65];   // [k][m] (+1 pad)
    __shared__ __align__(16) float Bs[128][64];   // [k][n]
    int tid   = threadIdx.x;
    int mbase = blockIdx.y * 64;
    int nbase = blockIdx.x * 64;

    // load A tile (transpose into [k][m])
    #pragma unroll
    for (int l = 0; l < 8; l++) {
        int fi = tid + l * 256;       // float4 id 0..2047
        int mm = fi >> 5;             // 0..63
        int k4 = fi & 31;             // 0..31
        int gm = mbase + mm;
        float4 v = make_float4(0.f, 0.f, 0.f, 0.f);
        if (gm < NN) v = *(const float4*)(emb + (size_t)gm * HID + k4 * 4);
        As[k4*4+0][mm] = v.x; As[k4*4+1][mm] = v.y;
        As[k4*4+2][mm] = v.z; As[k4*4+3][mm] = v.w;
    }
    // load B tile: W1cat[k][nbase+nn]
    #pragma unroll
    for (int l = 0; l < 8; l++) {
        int fi = tid + l * 256;       // 0..2047
        int kk = fi >> 4;             // 0..127
        int n4 = fi & 15;             // 0..15
        int gn = nbase + n4 * 4;
        const float* src = (gn < H4) ? (W1 + (size_t)kk * H4 + gn)
                                     : (W1 + (size_t)(128 + kk) * H4 + (gn - H4));
        *(float4*)&Bs[kk][n4 * 4] = *(const float4*)src;
    }
    __syncthreads();

    int tx = tid & 15, ty = tid >> 4;
    int tm = ty * 4, tn = tx * 4;
    float acc[4][4];
    #pragma unroll
    for (int i = 0; i < 4; i++)
        #pragma unroll
        for (int j = 0; j < 4; j++) acc[i][j] = 0.f;

    #pragma unroll 16
    for (int k = 0; k < 128; k++) {
        float a0 = As[k][tm], a1 = As[k][tm+1], a2 = As[k][tm+2], a3 = As[k][tm+3];
        float4 b = *(const float4*)&Bs[k][tn];
        acc[0][0] += a0*b.x; acc[0][1] += a0*b.y; acc[0][2] += a0*b.z; acc[0][3] += a0*b.w;
        acc[1][0] += a1*b.x; acc[1][1] += a1*b.y; acc[1][2] += a1*b.z; acc[1][3] += a1*b.w;
        acc[2][0] += a2*b.x; acc[2][1] += a2*b.y; acc[2][2] += a2*b.z; acc[2][3] += a2*b.w;
        acc[3][0] += a3*b.x; acc[3][1] += a3*b.y; acc[3][2] += a3*b.z; acc[3][3] += a3*b.w;
    }
    #pragma unroll
    for (int i = 0; i < 4; i++) {
        int gm = mbase + tm + i;
        if (gm < NN)
            *(float4*)(g_PQ + (size_t)gm * PQW + nbase + tn) =
                make_float4(acc[i][0], acc[i][1], acc[i][2], acc[i][3]);
    }
}

// ---------------- K2: edge attention, one warp per edge ----------------
__global__ __launch_bounds__(256) void k_edge_att(const int* __restrict__ ei,
                                                  const float* __restrict__ b1,
                                                  const float* __restrict__ W2,
                                                  const float* __restrict__ b2,
                                                  float* __restrict__ out) {
    __shared__ __align__(16) float sb1[H4];
    __shared__ __align__(16) float sw2[H4];
    int tid = threadIdx.x;
    for (int i = tid; i < H4; i += blockDim.x) { sb1[i] = b1[i]; sw2[i] = W2[i]; }
    __syncthreads();

    int gw   = (blockIdx.x * blockDim.x + tid) >> 5;
    int lane = tid & 31;
    if (gw >= NE) return;
    int r = ei[gw];
    int c = ei[NE + gw];
    const float4* Pr = (const float4*)(g_PQ + (size_t)r * PQW);
    const float4* Qr = (const float4*)(g_PQ + (size_t)c * PQW + H4);
    const float4* B4 = (const float4*)sb1;
    const float4* W4 = (const float4*)sw2;

    float acc = 0.f;
    #pragma unroll
    for (int it = 0; it < 4; it++) {
        int j4 = it * 32 + lane;      // float4 index 0..127 (512 floats)
        float4 p = Pr[j4];
        float4 q = Qr[j4];
        float4 bb = B4[j4];
        float4 ww = W4[j4];
        acc += ww.x * fmaxf(p.x + q.x + bb.x, 0.f);
        acc += ww.y * fmaxf(p.y + q.y + bb.y, 0.f);
        acc += ww.z * fmaxf(p.z + q.z + bb.z, 0.f);
        acc += ww.w * fmaxf(p.w + q.w + bb.w, 0.f);
    }
    #pragma unroll
    for (int off = 16; off > 0; off >>= 1)
        acc += __shfl_xor_sync(0xFFFFFFFFu, acc, off);
    if (lane == 0) out[O_ATT + gw] = acc + b2[0];
}

// ---------------- K3: per-graph top-k radix select + mask/weights ----------------
__global__ __launch_bounds__(256) void k_select(const int* __restrict__ ei,
                                                float* __restrict__ out) {
    __shared__ unsigned int skey[EPG];
    __shared__ int hist[256];
    __shared__ int tcnt[256];
    __shared__ unsigned int s_prefix;
    __shared__ int s_kleft;

    int g    = blockIdx.x;
    int tid  = threadIdx.x;
    int base = g * EPG;

    for (int i = tid; i < EPG; i += 256) skey[i] = f2k(out[O_ATT + base + i]);
    __syncthreads();

    unsigned int prefix = 0u;
    int kleft = KSEL;
    for (int pass = 3; pass >= 0; pass--) {
        int shift = pass * 8;
        hist[tid] = 0;
        __syncthreads();
        unsigned int maskHigh = (pass == 3) ? 0u : (0xFFFFFFFFu << (shift + 8));
        for (int i = tid; i < EPG; i += 256) {
            unsigned int k = skey[i];
            if ((k & maskHigh) == prefix)
                atomicAdd(&hist[(k >> shift) & 255], 1);
        }
        __syncthreads();
        if (tid == 0) {
            int cum = 0, sel = 0;
            for (int b = 255; b >= 0; b--) {
                int c = hist[b];
                if (cum + c >= kleft) { sel = b; kleft -= cum; break; }
                cum += c;
            }
            s_prefix = prefix | ((unsigned int)sel << shift);
            s_kleft  = kleft;
        }
        __syncthreads();
        prefix = s_prefix;
        kleft  = s_kleft;
        __syncthreads();
    }
    unsigned int T = prefix;   // key of the KSEL-th largest
    int need = kleft;          // how many ==T to take (first-by-index)

    // ordered prefix over equality flags (contiguous 16-elem chunks per thread)
    int start = tid * 16;
    int localEq = 0;
    for (int i = start; i < start + 16 && i < EPG; i++) localEq += (skey[i] == T);
    tcnt[tid] = localEq;
    __syncthreads();
    for (int off = 1; off < 256; off <<= 1) {
        int v = (tid >= off) ? tcnt[tid - off] : 0;
        __syncthreads();
        tcnt[tid] += v;
        __syncthreads();
    }
    int run = tcnt[tid] - localEq;   // exclusive prefix of equals before my chunk

    for (int i = start; i < start + 16 && i < EPG; i++) {
        unsigned int k = skey[i];
        bool causal;
        if (k > T)       causal = true;
        else if (k == T) { causal = (run < need); run++; }
        else             causal = false;
        float att = k2f(k);
        int e = base + i;
        out[O_CW + e] = causal ? att : 0.f;
        out[O_SW + e] = causal ? 0.f : att;
        out[O_CM + e] = causal ? 1.f : 0.f;
        g_cmask[e] = causal ? 1 : 0;
        if (causal) {
            g_nm[ei[e]]      = 1;   // benign races: all write 1
            g_nm[ei[NE + e]] = 1;
        }
    }
}

// ---------------- K4/K5: two-level scan of node mask ----------------
__global__ __launch_bounds__(512) void k_scan_a() {
    __shared__ int s[512];
    int tid = threadIdx.x;
    int n = blockIdx.x * 512 + tid;
    int x = (n < NN) ? g_nm[n] : 0;
    s[tid] = x;
    __syncthreads();
    for (int off = 1; off < 512; off <<= 1) {
        int v = (tid >= off) ? s[tid - off] : 0;
        __syncthreads();
        s[tid] += v;
        __syncthreads();
    }
    if (n < NN) g_scan[n] = s[tid];
    if (tid == 511) g_bsum[blockIdx.x] = s[511];
}

__global__ void k_scan_b(int nblk) {
    if (threadIdx.x == 0 && blockIdx.x == 0) {
        int running = 0;
        for (int b = 0; b < nblk; b++) {
            int t = g_bsum[b];
            g_bsum[b] = running;
            running += t;
        }
    }
}

// ---------------- K6: new_id + node_mask output ----------------
__global__ void k_finalize_nodes(float* __restrict__ out) {
    int n = blockIdx.x * blockDim.x + threadIdx.x;
    if (n >= NN) return;
    int incl = g_scan[n] + g_bsum[n >> 9];
    g_newid[n] = incl - 1;
    out[O_NM + n] = g_nm[n] ? 1.f : 0.f;
}

// ---------------- K7: causal_x (masked embeddings), thread per float4 ----------------
__global__ void k_causal_x(const float* __restrict__ emb, float* __restrict__ out) {
    int i = blockIdx.x * blockDim.x + threadIdx.x;   // float4 index over [NN*32]
    if (i >= NN * 32) return;
    int node = i >> 5;
    float4 v = make_float4(0.f, 0.f, 0.f, 0.f);
    if (g_nm[node]) v = ((const float4*)emb)[i];
    ((float4*)(out + O_CX))[i] = v;
}

// ---------------- K8: relabeled edge index ----------------
__global__ void k_edge_out(const int* __restrict__ ei, float* __restrict__ out) {
    int e = blockIdx.x * blockDim.x + threadIdx.x;
    if (e >= NE) return;
    bool c = g_cmask[e] != 0;
    int r = ei[e], cc = ei[NE + e];
    out[O_EI + e]      = c ? (float)g_newid[r]  : -1.f;
    out[O_EI + NE + e] = c ? (float)g_newid[cc] : -1.f;
}

// ---------------- launch ----------------
extern "C" void kernel_launch(void* const* d_in, const int* in_sizes, int n_in,
                              void* d_out, int out_size) {
    const float* emb = (const float*)d_in[0];
    const int*   ei  = (const int*)d_in[1];
    // d_in[2] = node_batch (implied by layout: graph = e / EPG)
    const float* W1  = (const float*)d_in[3];
    const float* b1  = (const float*)d_in[4];
    const float* W2  = (const float*)d_in[5];
    const float* b2  = (const float*)d_in[6];
    float* out = (float*)d_out;

    k_zero_nm<<<(NN + 255) / 256, 256>>>();

    dim3 ggrid(PQW / 64, (NN + 63) / 64);   // (16, 782)
    k_gemm_pq<<<ggrid, 256>>>(emb, W1);

    k_edge_att<<<(NE * 32 + 255) / 256, 256>>>(ei, b1, W2, b2, out);

    k_select<<<NG, 256>>>(ei, out);

    int nblk = (NN + 511) / 512;            // 98
    k_scan_a<<<nblk, 512>>>();
    k_scan_b<<<1, 32>>>(nblk);

    k_finalize_nodes<<<(NN + 255) / 256, 256>>>(out);
    k_causal_x<<<(NN * 32 + 255) / 256, 256>>>(emb, out);
    k_edge_out<<<(NE + 255) / 256, 256>>>(ei, out);
}

// round 2
// speedup vs baseline: 1.2523x; 1.2523x over previous
#include <cuda_runtime.h>
#include <math.h>

// ---------------- problem constants (fixed by reference) ----------------
#define NG   100
#define NPG  500
#define EPG  4000
#define NN   (NG*NPG)      // 50000 nodes
#define NE   (NG*EPG)      // 400000 edges
#define HID  128
#define H4   512
#define PQW  1024          // P (512) || Q (512)
#define KSEL 2000          // ceil(0.5 * 4000)

// output layout (float32, concatenated in reference return order)
#define O_ATT 0
#define O_CW  (NE)
#define O_SW  (2*NE)
#define O_CM  (3*NE)
#define O_EI  (4*NE)           // [2,E]: new_row then new_col
#define O_NM  (6*NE)
#define O_CX  (6*NE + NN)

// ---------------- scratch (__device__ globals; no allocation) ----------------
__device__ float         g_PQ[(size_t)NN * PQW];   // ~205 MB
__device__ unsigned char g_cmask[NE];
__device__ int           g_nm[NN];
__device__ int           g_scan[NN];
__device__ int           g_newid[NN];
__device__ int           g_bsum[128];

typedef unsigned long long u64;

// ---------------- f32x2 packed-FMA helpers (Blackwell FFMA2 path) ----------------
__device__ __forceinline__ u64 pack2(float lo, float hi) {
    u64 r; asm("mov.b64 %0, {%1,%2};" : "=l"(r) : "f"(lo), "f"(hi)); return r;
}
__device__ __forceinline__ void fma2(u64& d, u64 a, u64 b) {
    asm("fma.rn.f32x2 %0, %1, %2, %0;" : "+l"(d) : "l"(a), "l"(b));
}
__device__ __forceinline__ void unpack2(u64 v, float& lo, float& hi) {
    asm("mov.b64 {%0,%1}, %2;" : "=f"(lo), "=f"(hi) : "l"(v));
}

// ---------------- ordered-key helpers ----------------
__device__ __forceinline__ unsigned int f2k(float f) {
    unsigned int u = __float_as_uint(f);
    return (u & 0x80000000u) ? ~u : (u | 0x80000000u);
}
__device__ __forceinline__ float k2f(unsigned int k) {
    unsigned int u = (k & 0x80000000u) ? (k & 0x7FFFFFFFu) : ~k;
    return __uint_as_float(u);
}

// ---------------- K0: zero node-mask ----------------
__global__ void k_zero_nm() {
    int n = blockIdx.x * blockDim.x + threadIdx.x;
    if (n < NN) g_nm[n] = 0;
}

// ---------------- K1: GEMM  PQ[n,0:512]=emb@W1[:128]+b1, PQ[n,512:1024]=emb@W1[128:] ----------------
// M=50000, N=1024, K=128. BM=BN=128, 256 thr, 8x8 microtile, f32x2 packed FMA.
// A staged [k][m] with float4-granular XOR swizzle (p = m4 ^ (k4&7)); B staged [k][n] directly.
extern __shared__ float smem_dyn[];
__global__ __launch_bounds__(256, 1) void k_gemm_pq(const float* __restrict__ emb,
                                                    const float* __restrict__ W1,
                                                    const float* __restrict__ b1) {
    float* As = smem_dyn;              // [128 k][32 float4 m] swizzled, 64KB
    float* Bs = smem_dyn + 128 * 128;  // [128 k][128 n], 64KB
    int tid   = threadIdx.x;
    int mbase = blockIdx.y * 128;
    int nbase = blockIdx.x * 128;

    // ---- load A tile with 4x4 register transpose + swizzle ----
    #pragma unroll
    for (int l = 0; l < 4; l++) {
        int t  = tid + l * 256;       // 0..1023
        int k4 = t & 31;              // float4 index along K
        int rb = t >> 5;              // row-block of 4 (0..31)
        float4 v[4];
        #pragma unroll
        for (int i = 0; i < 4; i++) {
            int gm = mbase + rb * 4 + i;
            v[i] = (gm < NN) ? *(const float4*)(emb + (size_t)gm * HID + k4 * 4)
                             : make_float4(0.f, 0.f, 0.f, 0.f);
        }
        const float* vv = (const float*)v;
        int p = rb ^ (k4 & 7);        // swizzled m4 position
        #pragma unroll
        for (int c = 0; c < 4; c++) {
            *(float4*)(As + (4 * k4 + c) * 128 + p * 4) =
                make_float4(vv[0 * 4 + c], vv[1 * 4 + c], vv[2 * 4 + c], vv[3 * 4 + c]);
        }
    }
    // ---- load B tile (direct, W1 is already [k][n]) ----
    bool isQ = (nbase >= H4);
    const float* Wbase = W1 + (isQ ? (size_t)HID * H4 : 0);
    int ncol = isQ ? (nbase - H4) : nbase;
    #pragma unroll
    for (int l = 0; l < 16; l++) {
        int t  = tid + l * 256;       // 0..4095
        int kk = t >> 5;
        int n4 = t & 31;
        *(float4*)(Bs + kk * 128 + n4 * 4) =
            *(const float4*)(Wbase + (size_t)kk * H4 + ncol + n4 * 4);
    }
    __syncthreads();

    int tx = tid & 15, ty = tid >> 4;
    int m0 = ty * 8, n0g = nbase + tx * 8;

    u64 acc[4][8];                    // [m-pair][n]
    #pragma unroll
    for (int p = 0; p < 4; p++)
        #pragma unroll
        for (int n = 0; n < 8; n++) acc[p][n] = 0ull;

    #pragma unroll 4
    for (int k = 0; k < 128; k++) {
        int swz = (k >> 2) & 7;
        float4 a0 = *(const float4*)(As + k * 128 + ((ty * 2)     ^ swz) * 4);
        float4 a1 = *(const float4*)(As + k * 128 + ((ty * 2 + 1) ^ swz) * 4);
        float4 b0 = *(const float4*)(Bs + k * 128 + tx * 8);
        float4 b1v = *(const float4*)(Bs + k * 128 + tx * 8 + 4);
        u64 am[4];
        am[0] = pack2(a0.x, a0.y); am[1] = pack2(a0.z, a0.w);
        am[2] = pack2(a1.x, a1.y); am[3] = pack2(a1.z, a1.w);
        u64 bb[8];
        bb[0] = pack2(b0.x, b0.x);  bb[1] = pack2(b0.y, b0.y);
        bb[2] = pack2(b0.z, b0.z);  bb[3] = pack2(b0.w, b0.w);
        bb[4] = pack2(b1v.x, b1v.x); bb[5] = pack2(b1v.y, b1v.y);
        bb[6] = pack2(b1v.z, b1v.z); bb[7] = pack2(b1v.w, b1v.w);
        #pragma unroll
        for (int p = 0; p < 4; p++)
            #pragma unroll
            for (int n = 0; n < 8; n++)
                fma2(acc[p][n], am[p], bb[n]);
    }

    // ---- epilogue: fold b1 into P half, store ----
    float badd[8];
    #pragma unroll
    for (int n = 0; n < 8; n++)
        badd[n] = (n0g + n < H4) ? b1[n0g + n] : 0.f;

    #pragma unroll
    for (int p = 0; p < 4; p++) {
        float lo[8], hi[8];
        #pragma unroll
        for (int n = 0; n < 8; n++) unpack2(acc[p][n], lo[n], hi[n]);
        int gm0 = mbase + m0 + 2 * p;
        if (gm0 < NN) {
            float4 s0 = make_float4(lo[0]+badd[0], lo[1]+badd[1], lo[2]+badd[2], lo[3]+badd[3]);
            float4 s1 = make_float4(lo[4]+badd[4], lo[5]+badd[5], lo[6]+badd[6], lo[7]+badd[7]);
            *(float4*)(g_PQ + (size_t)gm0 * PQW + n0g)     = s0;
            *(float4*)(g_PQ + (size_t)gm0 * PQW + n0g + 4) = s1;
        }
        if (gm0 + 1 < NN) {
            float4 s0 = make_float4(hi[0]+badd[0], hi[1]+badd[1], hi[2]+badd[2], hi[3]+badd[3]);
            float4 s1 = make_float4(hi[4]+badd[4], hi[5]+badd[5], hi[6]+badd[6], hi[7]+badd[7]);
            *(float4*)(g_PQ + (size_t)(gm0 + 1) * PQW + n0g)     = s0;
            *(float4*)(g_PQ + (size_t)(gm0 + 1) * PQW + n0g + 4) = s1;
        }
    }
}

// ---------------- K2: edge attention, one warp per edge (b1 pre-folded into P) ----------------
__global__ __launch_bounds__(256) void k_edge_att(const int* __restrict__ ei,
                                                  const float* __restrict__ W2,
                                                  const float* __restrict__ b2,
                                                  float* __restrict__ out) {
    __shared__ __align__(16) float sw2[H4];
    int tid = threadIdx.x;
    for (int i = tid; i < H4; i += blockDim.x) sw2[i] = W2[i];
    __syncthreads();

    int gw   = (blockIdx.x * blockDim.x + tid) >> 5;
    int lane = tid & 31;
    if (gw >= NE) return;
    int r = ei[gw];
    int c = ei[NE + gw];
    const float4* Pr = (const float4*)(g_PQ + (size_t)r * PQW);
    const float4* Qr = (const float4*)(g_PQ + (size_t)c * PQW + H4);
    const float4* W4 = (const float4*)sw2;

    float acc = 0.f;
    #pragma unroll
    for (int it = 0; it < 4; it++) {
        int j4 = it * 32 + lane;
        float4 p = Pr[j4];
        float4 q = Qr[j4];
        float4 ww = W4[j4];
        acc += ww.x * fmaxf(p.x + q.x, 0.f);
        acc += ww.y * fmaxf(p.y + q.y, 0.f);
        acc += ww.z * fmaxf(p.z + q.z, 0.f);
        acc += ww.w * fmaxf(p.w + q.w, 0.f);
    }
    #pragma unroll
    for (int off = 16; off > 0; off >>= 1)
        acc += __shfl_xor_sync(0xFFFFFFFFu, acc, off);
    if (lane == 0) out[O_ATT + gw] = acc + b2[0];
}

// ---------------- K3: per-graph top-k radix select (512 thr, parallel bucket scan) ----------------
__global__ __launch_bounds__(512) void k_select(const int* __restrict__ ei,
                                                float* __restrict__ out) {
    __shared__ unsigned int skey[EPG];     // 16KB
    __shared__ int hist[256];
    __shared__ int sscan[512];
    __shared__ unsigned int s_prefix;
    __shared__ int s_kleft;

    int g    = blockIdx.x;
    int tid  = threadIdx.x;
    int base = g * EPG;

    for (int i = tid; i < EPG; i += 512) skey[i] = f2k(out[O_ATT + base + i]);
    __syncthreads();

    unsigned int prefix = 0u;
    int kleft = KSEL;
    #pragma unroll
    for (int pass = 3; pass >= 0; pass--) {
        int shift = pass * 8;
        if (tid < 256) hist[tid] = 0;
        __syncthreads();
        unsigned int maskHigh = (pass == 3) ? 0u : (0xFFFFFFFFu << (shift + 8));
        for (int i = tid; i < EPG; i += 512) {
            unsigned int k = skey[i];
            if ((k & maskHigh) == prefix)
                atomicAdd(&hist[(k >> shift) & 255], 1);
        }
        __syncthreads();
        // inclusive suffix sum over 256 buckets (threads 0..255)
        int v = (tid < 256) ? hist[tid] : 0;
        sscan[tid] = v;
        __syncthreads();
        #pragma unroll
        for (int off = 1; off < 256; off <<= 1) {
            int add = (tid + off < 256) ? sscan[tid + off] : 0;
            __syncthreads();
            if (tid < 256) sscan[tid] += add;
            __syncthreads();
        }
        if (tid < 256) {
            int incl  = sscan[tid];       // sum of buckets >= tid
            int above = incl - hist[tid]; // sum of buckets  > tid
            if (above < kleft && incl >= kleft) {
                s_prefix = prefix | ((unsigned int)tid << shift);
                s_kleft  = kleft - above;
            }
        }
        __syncthreads();
        prefix = s_prefix;
        kleft  = s_kleft;
        __syncthreads();
    }
    unsigned int T = prefix;   // key of the KSEL-th largest
    int need = kleft;          // how many ==T to take (first-by-index)

    // ordered prefix over equality flags (contiguous 8-elem chunks per thread)
    int start = tid * 8;
    int localEq = 0;
    for (int i = start; i < start + 8 && i < EPG; i++) localEq += (skey[i] == T);
    sscan[tid] = localEq;
    __syncthreads();
    #pragma unroll
    for (int off = 1; off < 512; off <<= 1) {
        int v = (tid >= off) ? sscan[tid - off] : 0;
        __syncthreads();
        sscan[tid] += v;
        __syncthreads();
    }
    int run = sscan[tid] - localEq;   // exclusive prefix of equals before my chunk

    for (int i = start; i < start + 8 && i < EPG; i++) {
        unsigned int k = skey[i];
        bool causal;
        if (k > T)       causal = true;
        else if (k == T) { causal = (run < need); run++; }
        else             causal = false;
        float att = k2f(k);
        int e = base + i;
        out[O_CW + e] = causal ? att : 0.f;
        out[O_SW + e] = causal ? 0.f : att;
        out[O_CM + e] = causal ? 1.f : 0.f;
        g_cmask[e] = causal ? 1 : 0;
        if (causal) {
            g_nm[ei[e]]      = 1;   // benign races: all write 1
            g_nm[ei[NE + e]] = 1;
        }
    }
}

// ---------------- K4/K5: two-level scan of node mask ----------------
__global__ __launch_bounds__(512) void k_scan_a() {
    __shared__ int s[512];
    int tid = threadIdx.x;
    int n = blockIdx.x * 512 + tid;
    int x = (n < NN) ? g_nm[n] : 0;
    s[tid] = x;
    __syncthreads();
    for (int off = 1; off < 512; off <<= 1) {
        int v = (tid >= off) ? s[tid - off] : 0;
        __syncthreads();
        s[tid] += v;
        __syncthreads();
    }
    if (n < NN) g_scan[n] = s[tid];
    if (tid == 511) g_bsum[blockIdx.x] = s[511];
}

__global__ void k_scan_b(int nblk) {
    if (threadIdx.x == 0 && blockIdx.x == 0) {
        int running = 0;
        for (int b = 0; b < nblk; b++) {
            int t = g_bsum[b];
            g_bsum[b] = running;
            running += t;
        }
    }
}

// ---------------- K6: new_id + node_mask output ----------------
__global__ void k_finalize_nodes(float* __restrict__ out) {
    int n = blockIdx.x * blockDim.x + threadIdx.x;
    if (n >= NN) return;
    int incl = g_scan[n] + g_bsum[n >> 9];
    g_newid[n] = incl - 1;
    out[O_NM + n] = g_nm[n] ? 1.f : 0.f;
}

// ---------------- K7: causal_x (masked embeddings), thread per float4 ----------------
__global__ void k_causal_x(const float* __restrict__ emb, float* __restrict__ out) {
    int i = blockIdx.x * blockDim.x + threadIdx.x;   // float4 index over [NN*32]
    if (i >= NN * 32) return;
    int node = i >> 5;
    float4 v = make_float4(0.f, 0.f, 0.f, 0.f);
    if (g_nm[node]) v = ((const float4*)emb)[i];
    ((float4*)(out + O_CX))[i] = v;
}

// ---------------- K8: relabeled edge index ----------------
__global__ void k_edge_out(const int* __restrict__ ei, float* __restrict__ out) {
    int e = blockIdx.x * blockDim.x + threadIdx.x;
    if (e >= NE) return;
    bool c = g_cmask[e] != 0;
    int r = ei[e], cc = ei[NE + e];
    out[O_EI + e]      = c ? (float)g_newid[r]  : -1.f;
    out[O_EI + NE + e] = c ? (float)g_newid[cc] : -1.f;
}

// ---------------- launch ----------------
extern "C" void kernel_launch(void* const* d_in, const int* in_sizes, int n_in,
                              void* d_out, int out_size) {
    const float* emb = (const float*)d_in[0];
    const int*   ei  = (const int*)d_in[1];
    // d_in[2] = node_batch (implied by layout: graph = e / EPG)
    const float* W1  = (const float*)d_in[3];
    const float* b1  = (const float*)d_in[4];
    const float* W2  = (const float*)d_in[5];
    const float* b2  = (const float*)d_in[6];
    float* out = (float*)d_out;

    k_zero_nm<<<(NN + 255) / 256, 256>>>();

    const int GEMM_SMEM = 128 * 128 * 4 * 2;   // 128KB
    cudaFuncSetAttribute(k_gemm_pq, cudaFuncAttributeMaxDynamicSharedMemorySize, GEMM_SMEM);
    dim3 ggrid(PQW / 128, (NN + 127) / 128);   // (8, 391)
    k_gemm_pq<<<ggrid, 256, GEMM_SMEM>>>(emb, W1, b1);

    k_edge_att<<<(NE * 32 + 255) / 256, 256>>>(ei, W2, b2, out);

    k_select<<<NG, 512>>>(ei, out);

    int nblk = (NN + 511) / 512;            // 98
    k_scan_a<<<nblk, 512>>>();
    k_scan_b<<<1, 32>>>(nblk);

    k_finalize_nodes<<<(NN + 255) / 256, 256>>>(out);
    k_causal_x<<<(NN * 32 + 255) / 256, 256>>>(emb, out);
    k_edge_out<<<(NE + 255) / 256, 256>>>(ei, out);
}